// round 1
// baseline (speedup 1.0000x reference)
#include <cuda_runtime.h>
#include <math.h>

// Problem constants
#define BHALF 8192            // B
#define N     16384           // 2B
#define TILE  128
#define NT    (N / TILE)      // 128 tiles
#define EXP2F_CONST 7.389056098930650f   // exp(2) = exp(sim_ii / T)
#define C_2LOG2E    2.885390081777927f   // 2 * log2(e)
#define TEMP_EPS    0.01f

// Scratch: partial row sums. g_part[k*N + i] = sum over columns j in tile k of
// exp(sim(i,j)/T). Each (k,i) slot has exactly one writer -> deterministic.
__device__ float g_part[NT * N];          // 8 MB
__device__ float g_blocksum[64];          // per-block log-denominator sums

// ---------------------------------------------------------------------------
// Kernel A: symmetric tile kernel. Grid (NT, NT); block 256 threads.
// Block (a=by, b=bx) with a<=b computes the 128x128 tile of
// e = exp(2/(1+|r_i - r_j|)) and writes:
//   row partials  -> g_part[b][rows of tile a]
//   col partials  -> g_part[a][rows of tile b]   (skipped when a==b)
// ---------------------------------------------------------------------------
__global__ __launch_bounds__(256) void tile_kernel(
    const float* __restrict__ emb_i, const float* __restrict__ emb_j)
{
    const int b = blockIdx.x;
    const int a = blockIdx.y;
    if (a > b) return;   // upper triangle only

    __shared__ float ra[TILE];
    __shared__ float rb[TILE];
    __shared__ float red[16][TILE + 1];   // +1 pad: conflict-free reduce

    const int t = threadIdx.x;

    // Cooperative load of rep values for both tiles.
    // rep[g] = g < B ? emb_i[g] : emb_j[g-B]
    if (t < TILE) {
        int g = a * TILE + t;
        ra[t] = (g < BHALF) ? emb_i[g] : emb_j[g - BHALF];
    } else {
        int t2 = t - TILE;
        int g = b * TILE + t2;
        rb[t2] = (g < BHALF) ? emb_i[g] : emb_j[g - BHALF];
    }
    __syncthreads();

    const int tx = t & 15;      // 16 thread-cols
    const int ty = t >> 4;      // 16 thread-rows
    float ri[8], rj[8];
#pragma unroll
    for (int y = 0; y < 8; y++) ri[y] = ra[ty * 8 + y];
#pragma unroll
    for (int x = 0; x < 8; x++) rj[x] = rb[tx * 8 + x];

    float rowacc[8], colacc[8];
#pragma unroll
    for (int k = 0; k < 8; k++) { rowacc[k] = 0.0f; colacc[k] = 0.0f; }

    // 64 pair evaluations per thread: 2 MUFU each (RCP + EX2), fully independent.
#pragma unroll
    for (int y = 0; y < 8; y++) {
#pragma unroll
        for (int x = 0; x < 8; x++) {
            float d = fabsf(ri[y] - rj[x]);
            float e = exp2f(__fdividef(C_2LOG2E, 1.0f + d));
            rowacc[y] += e;
            colacc[x] += e;
        }
    }

    // --- deterministic row-partial reduction (across the 16 thread-cols) ---
#pragma unroll
    for (int y = 0; y < 8; y++) red[tx][ty * 8 + y] = rowacc[y];
    __syncthreads();
    if (t < TILE) {
        float s = 0.0f;
#pragma unroll
        for (int k = 0; k < 16; k++) s += red[k][t];
        g_part[b * N + a * TILE + t] = s;
    }
    __syncthreads();

    // --- deterministic col-partial reduction (across the 16 thread-rows) ---
#pragma unroll
    for (int x = 0; x < 8; x++) red[ty][tx * 8 + x] = colacc[x];
    __syncthreads();
    if (a != b && t < TILE) {
        float s = 0.0f;
#pragma unroll
        for (int k = 0; k < 16; k++) s += red[k][t];
        g_part[a * N + b * TILE + t] = s;
    }
}

// ---------------------------------------------------------------------------
// Kernel B1: per-row denominator -> log -> block sums. Grid 64 x 256 threads.
// ---------------------------------------------------------------------------
__global__ __launch_bounds__(256) void rowlog_kernel()
{
    __shared__ float sred[256];
    const int i = blockIdx.x * 256 + threadIdx.x;   // row index, 0..N-1

    float s = 0.0f;
#pragma unroll 8
    for (int k = 0; k < NT; k++) s += g_part[k * N + i];   // coalesced over i
    float denom = s - EXP2F_CONST;                          // remove diagonal
    float l = logf(denom);

    sred[threadIdx.x] = l;
    __syncthreads();
    for (int off = 128; off > 0; off >>= 1) {
        if (threadIdx.x < off) sred[threadIdx.x] += sred[threadIdx.x + off];
        __syncthreads();
    }
    if (threadIdx.x == 0) g_blocksum[blockIdx.x] = sred[0];
}

// ---------------------------------------------------------------------------
// Kernel B2: prosody softmax + positives + final combine. 1 block, 256 threads.
// loss = (1/n) [ sum_i log(denom_i) + 2*sum_b log1p(|ei-ej|)
//                                   + 2*sum_b log(softmax_b + eps) ]
// ---------------------------------------------------------------------------
__global__ __launch_bounds__(256) void finalize_kernel(
    const float* __restrict__ emb_i, const float* __restrict__ emb_j,
    const float* __restrict__ pro_i, const float* __restrict__ pro_j,
    float* __restrict__ out)
{
    __shared__ float pd[BHALF];      // 32 KB: |pi - pj|
    __shared__ float sred[256];
    const int t = threadIdx.x;

    // pd + per-thread max
    float mx = -1.0f;
    for (int b = t; b < BHALF; b += 256) {
        float v = fabsf(pro_i[b] - pro_j[b]);
        pd[b] = v;
        mx = fmaxf(mx, v);
    }
    sred[t] = mx;
    __syncthreads();
    for (int off = 128; off > 0; off >>= 1) {
        if (t < off) sred[t] = fmaxf(sred[t], sred[t + off]);
        __syncthreads();
    }
    mx = sred[0];
    __syncthreads();

    // sum of exp(pd - mx)
    float se = 0.0f;
    for (int b = t; b < BHALF; b += 256) se += expf(pd[b] - mx);
    sred[t] = se;
    __syncthreads();
    for (int off = 128; off > 0; off >>= 1) {
        if (t < off) sred[t] += sred[t + off];
        __syncthreads();
    }
    float Z = sred[0];
    __syncthreads();

    // Lpros = sum_b log(softmax_b + eps) ; Lpos = sum_b log1p(|ei-ej|)
    float lp = 0.0f, lq = 0.0f;
    float invZ = 1.0f / Z;
    for (int b = t; b < BHALF; b += 256) {
        lp += logf(expf(pd[b] - mx) * invZ + TEMP_EPS);
        lq += log1pf(fabsf(emb_i[b] - emb_j[b]));
    }
    sred[t] = lp + lq;
    __syncthreads();
    for (int off = 128; off > 0; off >>= 1) {
        if (t < off) sred[t] += sred[t + off];
        __syncthreads();
    }
    float tail2 = sred[0];   // sum over b of (log(sm+eps) + log1p(d))
    __syncthreads();

    // add the 64 block sums of log(denom)
    if (t == 0) {
        float L1 = 0.0f;
        for (int k = 0; k < 64; k++) L1 += g_blocksum[k];
        out[0] = (L1 + 2.0f * tail2) / (float)N;
    }
}

// ---------------------------------------------------------------------------
extern "C" void kernel_launch(void* const* d_in, const int* in_sizes, int n_in,
                              void* d_out, int out_size)
{
    const float* emb_i = (const float*)d_in[0];
    const float* emb_j = (const float*)d_in[1];
    const float* pro_i = (const float*)d_in[2];
    const float* pro_j = (const float*)d_in[3];
    float* out = (float*)d_out;

    dim3 gridA(NT, NT);
    tile_kernel<<<gridA, 256>>>(emb_i, emb_j);
    rowlog_kernel<<<64, 256>>>();
    finalize_kernel<<<1, 256>>>(emb_i, emb_j, pro_i, pro_j, out);
}

// round 2
// speedup vs baseline: 1.1505x; 1.1505x over previous
#include <cuda_runtime.h>
#include <math.h>
#include <stdint.h>

// Problem constants
#define BHALF 8192            // B
#define N     16384           // 2B
#define TILE  128
#define NT    (N / TILE)      // 128 tiles
#define NTRI  (NT * (NT + 1) / 2)        // 8256 triangular blocks
#define EXPDIAG 7.389056098930650f       // exp(2) = exp(sim_ii / T)
#define NEG_INV_C (-0.34657359027997264f) // -1/(2*log2(e)) = -ln2/2
#define TEMP_EPS 0.01f

// Scratch: partial row sums. g_part[k*N + i] = sum over columns j in tile k of
// exp(sim(i,j)/T). Each (k,i) slot has exactly one writer -> deterministic.
__device__ float g_part[NT * N];          // 8 MB (L2-resident)
__device__ float g_blocksum[128];

// ---------------- packed f32x2 helpers (sm_100 family) ----------------
__device__ __forceinline__ unsigned long long pk2(float lo, float hi) {
    unsigned long long r;
    asm("mov.b64 %0, {%1, %2};" : "=l"(r) : "f"(lo), "f"(hi));
    return r;
}
__device__ __forceinline__ float lo2(unsigned long long v) {
    float f;
    asm("{ .reg .f32 t; mov.b64 {%0, t}, %1; }" : "=f"(f) : "l"(v));
    return f;
}
__device__ __forceinline__ float hi2(unsigned long long v) {
    float f;
    asm("{ .reg .f32 t; mov.b64 {t, %0}, %1; }" : "=f"(f) : "l"(v));
    return f;
}
__device__ __forceinline__ unsigned long long add2(unsigned long long a, unsigned long long b) {
    unsigned long long r;
    asm("add.rn.f32x2 %0, %1, %2;" : "=l"(r) : "l"(a), "l"(b));
    return r;
}
__device__ __forceinline__ unsigned long long mul2(unsigned long long a, unsigned long long b) {
    unsigned long long r;
    asm("mul.rn.f32x2 %0, %1, %2;" : "=l"(r) : "l"(a), "l"(b));
    return r;
}
__device__ __forceinline__ unsigned long long fma2(unsigned long long a, unsigned long long b,
                                                   unsigned long long c) {
    unsigned long long r;
    asm("fma.rn.f32x2 %0, %1, %2, %3;" : "=l"(r) : "l"(a), "l"(b), "l"(c));
    return r;
}
__device__ __forceinline__ float ex2a(float x) {
    float r;
    asm("ex2.approx.ftz.f32 %0, %1;" : "=f"(r) : "f"(x));
    return r;
}

// ---------------------------------------------------------------------------
// Kernel A: symmetric tile kernel, triangular 1D grid of NTRI blocks.
// Block (a,b), a<=b, computes the 128x128 tile of e = exp(2/(1+|r_i - r_j|)).
// Per 2 pairs (f32x2 packed):
//   diff2 = riP + (-rjP)                       ADD2
//   d2    = |diff2|                            2x LOP (alu)
//   s2n   = -(1+d)/C = fma2(d2, -1/C, -1/C)    FMA2
//   r0    = bithack rcp: 0xFEF311C3 - bits(s2n)  2x IADD (alu), positive result
//   2x Newton: t = fma2(s2n, r, 2); r = mul2(r, t)   4 fma ops
//   e = ex2(r2.lo), ex2(r2.hi)                 2x MUFU.EX2
//   rowaccP += e2 ; colaccP += e2              2x ADD2
// => fma pipe 8 ops (16cyc) and MUFU 2 ops (16cyc) per 2 pairs: co-bound.
// ---------------------------------------------------------------------------
__global__ __launch_bounds__(256, 2) void tile_kernel(
    const float* __restrict__ emb_i, const float* __restrict__ emb_j)
{
    // decode triangular (a, b) from linear block id
    const int k = blockIdx.x;
    float disc = (float)((2 * NT + 1) * (2 * NT + 1) - 8 * k);
    int a = (int)(((float)(2 * NT + 1) - sqrtf(disc)) * 0.5f);
    a = max(0, min(a, NT - 1));
    while (a > 0 && k < a * NT - (a * (a - 1)) / 2) a--;
    while (k >= (a + 1) * NT - ((a + 1) * a) / 2) a++;
    const int b = a + (k - (a * NT - (a * (a - 1)) / 2));

    __shared__ float ra[TILE];
    __shared__ float rbn[TILE];           // NEGATED b-tile values
    __shared__ float red[16][TILE + 1];

    const int t = threadIdx.x;

    if (t < TILE) {
        int g = a * TILE + t;
        ra[t] = (g < BHALF) ? emb_i[g] : emb_j[g - BHALF];
    } else {
        int t2 = t - TILE;
        int g = b * TILE + t2;
        float v = (g < BHALF) ? emb_i[g] : emb_j[g - BHALF];
        rbn[t2] = -v;
    }
    __syncthreads();

    const int tx = t & 15;
    const int ty = t >> 4;

    unsigned long long riP[8], rjn[4];
#pragma unroll
    for (int y = 0; y < 8; y++) {
        float v = ra[ty * 8 + y];
        riP[y] = pk2(v, v);
    }
#pragma unroll
    for (int x2 = 0; x2 < 4; x2++)
        rjn[x2] = pk2(rbn[tx * 8 + 2 * x2], rbn[tx * 8 + 2 * x2 + 1]);

    const unsigned long long cN   = pk2(NEG_INV_C, NEG_INV_C);
    const unsigned long long two2 = pk2(2.0f, 2.0f);

    unsigned long long rowP[8], colP[4];
#pragma unroll
    for (int y = 0; y < 8; y++) rowP[y] = 0ULL;
#pragma unroll
    for (int x2 = 0; x2 < 4; x2++) colP[x2] = 0ULL;

#pragma unroll
    for (int y = 0; y < 8; y++) {
        const unsigned long long rip = riP[y];
#pragma unroll
        for (int x2 = 0; x2 < 4; x2++) {
            unsigned long long df = add2(rip, rjn[x2]);              // ri - rj
            df &= 0x7FFFFFFF7FFFFFFFULL;                              // |.| per half
            unsigned long long sn = fma2(df, cN, cN);                 // -(1+d)/C
            uint32_t bl = (uint32_t)sn;
            uint32_t bh = (uint32_t)(sn >> 32);
            unsigned long long r = pk2(__uint_as_float(0xFEF311C3u - bl),
                                       __uint_as_float(0xFEF311C3u - bh));
            unsigned long long tt = fma2(sn, r, two2);                // 2 - s*r
            r = mul2(r, tt);
            tt = fma2(sn, r, two2);
            r = mul2(r, tt);                                          // ~ C/(1+d)
            unsigned long long e2 = pk2(ex2a(lo2(r)), ex2a(hi2(r)));
            rowP[y]  = add2(rowP[y],  e2);
            colP[x2] = add2(colP[x2], e2);
        }
    }

    // --- deterministic row-partial reduction (across the 16 thread-cols) ---
#pragma unroll
    for (int y = 0; y < 8; y++)
        red[tx][ty * 8 + y] = lo2(rowP[y]) + hi2(rowP[y]);
    __syncthreads();
    if (t < TILE) {
        float s = 0.0f;
#pragma unroll
        for (int kk = 0; kk < 16; kk++) s += red[kk][t];
        g_part[b * N + a * TILE + t] = s;
    }
    __syncthreads();

    // --- deterministic col-partial reduction (across the 16 thread-rows) ---
#pragma unroll
    for (int x2 = 0; x2 < 4; x2++) {
        red[ty][tx * 8 + 2 * x2]     = lo2(colP[x2]);
        red[ty][tx * 8 + 2 * x2 + 1] = hi2(colP[x2]);
    }
    __syncthreads();
    if (a != b && t < TILE) {
        float s = 0.0f;
#pragma unroll
        for (int kk = 0; kk < 16; kk++) s += red[kk][t];
        g_part[a * N + b * TILE + t] = s;
    }
}

// ---------------------------------------------------------------------------
// Kernel B1: per-row denominator -> log -> block sums. 128 blocks x 128 thr.
// ---------------------------------------------------------------------------
__global__ __launch_bounds__(128) void rowlog_kernel()
{
    __shared__ float sred[128];
    const int i = blockIdx.x * 128 + threadIdx.x;

    float s = 0.0f;
#pragma unroll 16
    for (int k = 0; k < NT; k++) s += g_part[k * N + i];
    float l = logf(s - EXPDIAG);    // remove diagonal term exp(2)

    sred[threadIdx.x] = l;
    __syncthreads();
    for (int off = 64; off > 0; off >>= 1) {
        if (threadIdx.x < off) sred[threadIdx.x] += sred[threadIdx.x + off];
        __syncthreads();
    }
    if (threadIdx.x == 0) g_blocksum[blockIdx.x] = sred[0];
}

// ---------------------------------------------------------------------------
// Kernel B2: prosody softmax + positives + final combine. 1 block, 512 thr.
// loss = (1/n) [ sum_i log(denom_i) + 2*sum_b log1p(|ei-ej|)
//                                   + 2*sum_b log(softmax_b + eps) ]
// ---------------------------------------------------------------------------
__global__ __launch_bounds__(512) void finalize_kernel(
    const float* __restrict__ emb_i, const float* __restrict__ emb_j,
    const float* __restrict__ pro_i, const float* __restrict__ pro_j,
    float* __restrict__ out)
{
    __shared__ float pd[BHALF];      // 32 KB
    __shared__ float sred[512];
    const int t = threadIdx.x;

    float mx = -1.0f;
    for (int b = t; b < BHALF; b += 512) {
        float v = fabsf(pro_i[b] - pro_j[b]);
        pd[b] = v;
        mx = fmaxf(mx, v);
    }
    sred[t] = mx;
    __syncthreads();
    for (int off = 256; off > 0; off >>= 1) {
        if (t < off) sred[t] = fmaxf(sred[t], sred[t + off]);
        __syncthreads();
    }
    mx = sred[0];
    __syncthreads();

    float se = 0.0f;
    for (int b = t; b < BHALF; b += 512) se += expf(pd[b] - mx);
    sred[t] = se;
    __syncthreads();
    for (int off = 256; off > 0; off >>= 1) {
        if (t < off) sred[t] += sred[t + off];
        __syncthreads();
    }
    float Z = sred[0];
    __syncthreads();

    float lp = 0.0f, lq = 0.0f;
    float invZ = 1.0f / Z;
    for (int b = t; b < BHALF; b += 512) {
        lp += logf(expf(pd[b] - mx) * invZ + TEMP_EPS);
        lq += log1pf(fabsf(emb_i[b] - emb_j[b]));
    }
    sred[t] = lp + lq;
    __syncthreads();
    for (int off = 256; off > 0; off >>= 1) {
        if (t < off) sred[t] += sred[t + off];
        __syncthreads();
    }
    float tail2 = sred[0];
    __syncthreads();

    if (t == 0) {
        float L1 = 0.0f;
        for (int k = 0; k < 128; k++) L1 += g_blocksum[k];
        out[0] = (L1 + 2.0f * tail2) / (float)N;
    }
}

// ---------------------------------------------------------------------------
extern "C" void kernel_launch(void* const* d_in, const int* in_sizes, int n_in,
                              void* d_out, int out_size)
{
    const float* emb_i = (const float*)d_in[0];
    const float* emb_j = (const float*)d_in[1];
    const float* pro_i = (const float*)d_in[2];
    const float* pro_j = (const float*)d_in[3];
    float* out = (float*)d_out;

    tile_kernel<<<NTRI, 256>>>(emb_i, emb_j);
    rowlog_kernel<<<128, 128>>>();
    finalize_kernel<<<1, 512>>>(emb_i, emb_j, pro_i, pro_j, out);
}